// round 1
// baseline (speedup 1.0000x reference)
#include <cuda_runtime.h>
#include <math.h>

#define EPSF 1e-12f
#define KFIX 64
#define S_TILE 32
#define B_TILE 256
#define THREADS 256

// Scratch: per-(s, interval) monomial coefficients (c0 + c1 t + c2 t^2 + c3 t^3).
// S=4096 rows x 64 slots (63 intervals + 1 pad).
__device__ float4 g_C[4096 * 64];

static __device__ __forceinline__ float sgnf(float v) {
    return (float)((v > 0.f) - (v < 0.f));
}

// One block per spline row s. blockDim.x == K (64).
// Computes PCHIP (Fritsch-Carlson) slopes, then monomial coefficients per interval.
__global__ void pchip_coeff_kernel(const float* __restrict__ coeffs,
                                   const float* __restrict__ knots,
                                   int S, int K) {
    __shared__ float sk[KFIX], sy[KFIX], sdel[KFIX], sd[KFIX];
    const int s = blockIdx.x;
    const int k = threadIdx.x;

    sk[k] = knots[k];
    sy[k] = coeffs[(size_t)s * K + k];
    __syncthreads();

    if (k < K - 1) {
        float h = sk[k + 1] - sk[k];
        sdel[k] = (sy[k + 1] - sy[k]) / (h + EPSF);
    }
    __syncthreads();

    float d;
    if (k == 0) {
        float h0 = sk[1] - sk[0], h1 = sk[2] - sk[1];
        float del0 = sdel[0], del1 = sdel[1];
        float d0 = ((2.f * h0 + h1) * del0 - h0 * del1) / (h0 + h1 + EPSF);
        if (sgnf(d0) != sgnf(del0)) d0 = 0.f;
        if ((sgnf(del0) != sgnf(del1)) && (fabsf(d0) > 3.f * fabsf(del0))) d0 = 3.f * del0;
        d = d0;
    } else if (k == K - 1) {
        float hn1 = sk[K - 1] - sk[K - 2], hn2 = sk[K - 2] - sk[K - 3];
        float deln1 = sdel[K - 2], deln2 = sdel[K - 3];
        float dn = ((2.f * hn1 + hn2) * deln1 - hn1 * deln2) / (hn1 + hn2 + EPSF);
        if (sgnf(dn) != sgnf(deln1)) dn = 0.f;
        if ((sgnf(deln1) != sgnf(deln2)) && (fabsf(dn) > 3.f * fabsf(deln1))) dn = 3.f * deln1;
        d = dn;
    } else {
        float dp = sdel[k - 1], dnx = sdel[k];
        float hp = sk[k] - sk[k - 1], hn = sk[k + 1] - sk[k];
        float w1 = 2.f * hn + hp;
        float w2 = hn + 2.f * hp;
        float denom = w1 / (dp + EPSF) + w2 / (dnx + EPSF);
        float di = (w1 + w2) / (denom + EPSF);
        d = (dp * dnx > 0.f) ? di : 0.f;
    }
    sd[k] = d;
    __syncthreads();

    float4 c = make_float4(0.f, 0.f, 0.f, 0.f);
    if (k < K - 1) {
        // Reference uses h = x1 - x0 + EPS inside the Hermite evaluation.
        float h = sk[k + 1] - sk[k] + EPSF;
        float y0 = sy[k], y1 = sy[k + 1];
        float d0 = sd[k], d1 = sd[k + 1];
        float dy = y1 - y0;
        c.x = y0;                                // t^0
        c.y = h * d0;                            // t^1
        c.z = 3.f * dy - h * (2.f * d0 + d1);    // t^2
        c.w = -2.f * dy + h * (d0 + d1);         // t^3
    }
    g_C[(size_t)s * K + k] = c;
}

// Eval: grid (S/32, B/256). Block = 8 b-rows x 32 s-cols; each thread walks
// B_TILE/8 rows. Coefficient tile staged in shared (padded 65 float4/row for
// bank rotation). Extrapolation handled via monomial endpoint identities:
//   below:  j=0, t<0,  r = c0 + c1*t                        (== y0 + d0*(x-x0))
//   above:  j=K-2, t>1, r = P(1) + P'(1)*(t-1)              (== yN + dN*(x-xN))
__global__ __launch_bounds__(THREADS) void pchip_eval_kernel(
    const float* __restrict__ xq, const float* __restrict__ knots,
    float* __restrict__ out, int B, int S) {
    __shared__ float4 tile[S_TILE][65];

    const int s0 = blockIdx.x * S_TILE;
    const int b0 = blockIdx.y * B_TILE;

    // Stage coefficient tile: 32 rows x 64 float4 = 32 KB, coalesced.
    const float4* Cbase = g_C + (size_t)s0 * KFIX;
    #pragma unroll
    for (int i = threadIdx.x; i < S_TILE * KFIX; i += THREADS) {
        int sl = i >> 6, j = i & 63;
        float4 v = make_float4(0.f, 0.f, 0.f, 0.f);
        if (s0 + sl < S) v = Cbase[i];
        tile[sl][j] = v;
    }
    __syncthreads();

    const float k0 = knots[0];
    const float inv_h = (float)(KFIX - 1) / (knots[KFIX - 1] - k0);

    const int sl = threadIdx.x & 31;
    const int s = s0 + sl;
    if (s >= S) return;
    const int bl0 = threadIdx.x >> 5;
    const int bmax = min(B_TILE, B - b0);

    #pragma unroll 4
    for (int bl = bl0; bl < bmax; bl += 8) {
        size_t off = (size_t)(b0 + bl) * S + s;
        float x = xq[off];
        float u = (x - k0) * inv_h;
        int j = (int)floorf(u);
        j = max(0, min(j, KFIX - 2));
        float t = u - (float)j;
        float4 c = tile[sl][j];

        float r = fmaf(t, fmaf(t, fmaf(t, c.w, c.z), c.y), c.x);
        if (t < 0.f) {
            r = fmaf(t, c.y, c.x);
        } else if (t > 1.f) {
            float p1 = c.x + c.y + c.z + c.w;            // P(1) = y_{K-1}
            float dp1 = fmaf(3.f, c.w, fmaf(2.f, c.z, c.y)); // P'(1) = h*d_{K-1}
            r = fmaf(t - 1.f, dp1, p1);
        }
        out[off] = r;
    }
}

extern "C" void kernel_launch(void* const* d_in, const int* in_sizes, int n_in,
                              void* d_out, int out_size) {
    const float* xq = (const float*)d_in[0];
    const float* coeffs = (const float*)d_in[1];
    const float* knots = (const float*)d_in[2];
    float* out = (float*)d_out;

    int K = in_sizes[2];          // 64
    int S = in_sizes[1] / K;      // 4096
    int B = in_sizes[0] / S;      // 4096

    pchip_coeff_kernel<<<S, K>>>(coeffs, knots, S, K);

    dim3 grid((S + S_TILE - 1) / S_TILE, (B + B_TILE - 1) / B_TILE);
    pchip_eval_kernel<<<grid, THREADS>>>(xq, knots, out, B, S);
}